// round 9
// baseline (speedup 1.0000x reference)
#include <cuda_runtime.h>
#include <stdint.h>

#define BB 1024
#define TT 1024
#define KK 48
#define START_TAG 46
#define STOP_TAG 47
#define NEGV (-10000.0f)
#define PADV (-3.0e38f)
#define NT 192                 // one sequence per block: 4 threads per 'next' tag

// forward-variable scratch: [t][seq][tag] (row t = fv BEFORE step t), +1 pad row
__device__ __align__(16) float g_fv[(size_t)(TT + 1) * BB * KK];

// monotone float -> ordered signed int (exact for all non-NaN floats)
__device__ __forceinline__ int fkey(float f) {
    int i = __float_as_int(f);
    return (i >= 0) ? i : (i ^ 0x7fffffff);
}

// exact argmax over 48 candidates: lane l holds index l (sa) and 32+l (sb, PADV
// for l>=16). Ties -> lowest index (matches jnp.argmax first occurrence).
__device__ __forceinline__ int argmax48(float sa, float sb, float* bout) {
    int ka = fkey(sa), kb = fkey(sb);
    int v = (ka > kb) ? ka : kb;
    int m;
    asm("redux.sync.max.s32 %0, %1, 0xffffffff;" : "=r"(m) : "r"(v));
    unsigned ba = __ballot_sync(0xffffffffu, ka == m);
    unsigned bb = __ballot_sync(0xffffffffu, kb == m);
    int idx = ba ? (__ffs((int)ba) - 1) : (31 + __ffs((int)bb));
    int mi = (m >= 0) ? m : (m ^ 0x7fffffff);
    *bout = __int_as_float(mi);
    return idx;
}

__global__ __launch_bounds__(NT, 7)
void viterbi_kernel(const float* __restrict__ feats,
                    const float* __restrict__ trans,
                    float* __restrict__ out)
{
    __shared__ __align__(16) float fv_sh[2][KK];
    __shared__ __align__(16) float trans_sh[KK * KK];
    __shared__ uint8_t path_sh[TT];

    const int tid = threadIdx.x;
    const int n   = tid >> 2;        // 'next' tag 0..47
    const int c   = tid & 3;         // quarter: prevs [c*12, c*12+12)
    const int seq = blockIdx.x;      // grid == BB

    // stage transitions into smem (used only by backtrack)
    for (int i2 = tid; i2 < KK * KK; i2 += NT) trans_sh[i2] = trans[i2];

    // this thread's 12 transition entries live in registers all T steps
    float tr[12];
    {
        const float4* tp = (const float4*)(trans + n * KK + c * 12);
#pragma unroll
        for (int k = 0; k < 3; k++) {
            float4 v = tp[k];
            tr[4 * k + 0] = v.x; tr[4 * k + 1] = v.y;
            tr[4 * k + 2] = v.z; tr[4 * k + 3] = v.w;
        }
    }

    if (tid < KK) fv_sh[0][tid] = (tid == START_TAG) ? 0.0f : NEGV;
    __syncthreads();

    const float* fbase = feats + (size_t)seq * TT * KK + n;
    float feat_next = fbase[0];
    float* sbase = g_fv + (size_t)seq * KK + n;      // + t*BB*KK

    // ---------------- forward pass: max-only ----------------
    int buf = 0;
#pragma unroll 4
    for (int t = 0; t < TT; t++) {
        float feat = feat_next;
        int tn = (t + 1 < TT) ? (t + 1) : (TT - 1);  // clamped prefetch
        feat_next = fbase[(size_t)tn * KK];

        const float4* fvr = reinterpret_cast<const float4*>(&fv_sh[buf][c * 12]);
        float4 v0 = fvr[0], v1 = fvr[1], v2 = fvr[2];
        float b0 = v0.x + tr[0], b1 = v0.y + tr[1];
        float b2 = v0.z + tr[2], b3 = v0.w + tr[3];
        b0 = fmaxf(b0, v1.x + tr[4]);  b1 = fmaxf(b1, v1.y + tr[5]);
        b2 = fmaxf(b2, v1.z + tr[6]);  b3 = fmaxf(b3, v1.w + tr[7]);
        b0 = fmaxf(b0, v2.x + tr[8]);  b1 = fmaxf(b1, v2.y + tr[9]);
        b2 = fmaxf(b2, v2.z + tr[10]); b3 = fmaxf(b3, v2.w + tr[11]);
        float b = fmaxf(fmaxf(b0, b1), fmaxf(b2, b3));
        // combine the 4 quarter-threads (adjacent lanes)
        b = fmaxf(b, __shfl_xor_sync(0xffffffffu, b, 1));
        b = fmaxf(b, __shfl_xor_sync(0xffffffffu, b, 2));
        float newfv = b + feat;
        if (c == 0) {
            fv_sh[buf ^ 1][n] = newfv;
            sbase[(size_t)(t + 1) * (BB * KK)] = newfv;     // row t+1 (padded)
        }
        __syncthreads();
        buf ^= 1;
    }

    // ---------------- terminal + backtrack (warp 0) ----------------
    if (tid < 32) {
        const int l = tid;
        float fa = fv_sh[buf][l];
        float fb = (l < 16) ? fv_sh[buf][32 + l] : 0.0f;
        float sa = fa + trans_sh[STOP_TAG * KK + l];
        float sb = (l < 16) ? (fb + trans_sh[STOP_TAG * KK + 32 + l]) : PADV;
        float best;
        int tag = argmax48(sa, sb, &best);
        if (l == 0) out[seq] = best;

        const float* rowbase = g_fv + (size_t)seq * KK;
        const size_t RSTR = (size_t)BB * KK;
        // 3-deep register prefetch of fv rows hides DRAM/L2 latency
        float a0 = rowbase[(size_t)(TT - 1) * RSTR + l];
        float e0 = (l < 16) ? rowbase[(size_t)(TT - 1) * RSTR + 32 + l] : 0.0f;
        float a1 = rowbase[(size_t)(TT - 2) * RSTR + l];
        float e1 = (l < 16) ? rowbase[(size_t)(TT - 2) * RSTR + 32 + l] : 0.0f;
        float a2 = rowbase[(size_t)(TT - 3) * RSTR + l];
        float e2 = (l < 16) ? rowbase[(size_t)(TT - 3) * RSTR + 32 + l] : 0.0f;

#define BT_STEP(T_, AA, EE, PF)                                              \
        {                                                                    \
            if (l == 0) path_sh[(T_)] = (uint8_t)tag;                        \
            float s_a = AA + trans_sh[tag * KK + l];                         \
            float s_b = (l < 16) ? (EE + trans_sh[tag * KK + 32 + l]) : PADV;\
            int rpf = ((PF) < 1) ? 1 : (PF);                                 \
            AA = rowbase[(size_t)rpf * RSTR + l];                            \
            EE = (l < 16) ? rowbase[(size_t)rpf * RSTR + 32 + l] : 0.0f;     \
            float bv;                                                        \
            tag = argmax48(s_a, s_b, &bv);                                   \
        }

        for (int t = TT - 1; t >= 3; t -= 3) {   // 1023 steps, divisible by 3
            BT_STEP(t,     a0, e0, t - 3)
            BT_STEP(t - 1, a1, e1, t - 4)
            BT_STEP(t - 2, a2, e2, t - 5)
        }
        if (l == 0) path_sh[0] = (uint8_t)tag;
#undef BT_STEP
    }
    __syncthreads();

    // ---------------- coalesced path dump ----------------
    float* pout = out + BB + (size_t)seq * TT;
    for (int t = tid; t < TT; t += NT) pout[t] = (float)path_sh[t];
}

extern "C" void kernel_launch(void* const* d_in, const int* in_sizes, int n_in,
                              void* d_out, int out_size) {
    (void)in_sizes; (void)n_in; (void)out_size;
    const float* feats = (const float*)d_in[0];
    const float* trans = (const float*)d_in[1];
    float* out = (float*)d_out;
    viterbi_kernel<<<BB, NT>>>(feats, trans, out);
}

// round 10
// speedup vs baseline: 1.3973x; 1.3973x over previous
#include <cuda_runtime.h>
#include <stdint.h>

#define BB 1024
#define TT 1024
#define KK 48
#define START_TAG 46
#define STOP_TAG 47
#define NEGV (-10000.0f)
#define PADV (-3.0e38f)
#define NT 96                  // one sequence per block: 2 threads per 'next' tag

// forward-variable scratch, layout [seq][tag][t]:
// index t holds fv AFTER step t (== fv BEFORE step t+1)
__device__ __align__(16) float g_fv[(size_t)BB * KK * TT];

// monotone float -> ordered signed int (exact for all non-NaN floats)
__device__ __forceinline__ int fkey(float f) {
    int i = __float_as_int(f);
    return (i >= 0) ? i : (i ^ 0x7fffffff);
}

// exact argmax over 48 candidates: lane l holds index l (sa) and 32+l (sb, PADV
// for l>=16). Ties -> lowest index (matches jnp.argmax first occurrence).
__device__ __forceinline__ int argmax48(float sa, float sb, float* bout) {
    int ka = fkey(sa), kb = fkey(sb);
    int v = (ka > kb) ? ka : kb;
    int m;
    asm("redux.sync.max.s32 %0, %1, 0xffffffff;" : "=r"(m) : "r"(v));
    unsigned ba = __ballot_sync(0xffffffffu, ka == m);
    unsigned bb = __ballot_sync(0xffffffffu, kb == m);
    int idx = ba ? (__ffs((int)ba) - 1) : (31 + __ffs((int)bb));
    int mi = (m >= 0) ? m : (m ^ 0x7fffffff);
    *bout = __int_as_float(mi);
    return idx;
}

__global__ __launch_bounds__(NT)
void viterbi_kernel(const float* __restrict__ feats,
                    const float* __restrict__ trans,
                    float* __restrict__ out)
{
    __shared__ __align__(16) float fv_sh[2][KK];
    __shared__ __align__(16) float trans_sh[KK * KK];
    __shared__ uint8_t path_sh[TT];

    const int tid = threadIdx.x;
    const int n   = tid >> 1;        // 'next' tag 0..47
    const int c   = tid & 1;         // half: prevs [c*24, c*24+24)
    const int seq = blockIdx.x;      // grid == BB

    // stage transitions into smem (used only by backtrack)
    for (int i2 = tid; i2 < KK * KK; i2 += NT) trans_sh[i2] = trans[i2];

    // this thread's 24 transition entries live in registers all T steps
    float tr[24];
#pragma unroll
    for (int k = 0; k < 24; k++) tr[k] = trans[n * KK + c * 24 + k];

    if (c == 0) fv_sh[0][n] = (n == START_TAG) ? 0.0f : NEGV;
    __syncthreads();

    const float* fbase = feats + (size_t)seq * TT * KK + n;
    // 2-deep feat prefetch
    float f_cur = fbase[0];
    float f_nxt = fbase[KK];
    float* sptr = g_fv + ((size_t)seq * KK + n) * TT;   // store cursor (c==0)

    // ---------------- forward pass: max-only ----------------
    int buf = 0;
    float vbuf0, vbuf1, vbuf2, vbuf3;
    for (int t = 0; t < TT; t += 4) {
#pragma unroll
        for (int k = 0; k < 4; k++) {
            const int tt = t + k;
            float feat = f_cur;
            f_cur = f_nxt;
            int tn = (tt + 2 < TT) ? (tt + 2) : (TT - 1);   // clamped prefetch
            f_nxt = fbase[(size_t)tn * KK];

            const float4* fvr =
                reinterpret_cast<const float4*>(&fv_sh[buf][c * 24]);
            float4 v0 = fvr[0];
            float b0 = v0.x + tr[0], b1 = v0.y + tr[1];
            float b2 = v0.z + tr[2], b3 = v0.w + tr[3];
#pragma unroll
            for (int q = 1; q < 6; q++) {
                float4 w = fvr[q];
                b0 = fmaxf(b0, w.x + tr[4 * q + 0]);
                b1 = fmaxf(b1, w.y + tr[4 * q + 1]);
                b2 = fmaxf(b2, w.z + tr[4 * q + 2]);
                b3 = fmaxf(b3, w.w + tr[4 * q + 3]);
            }
            float b = fmaxf(fmaxf(b0, b1), fmaxf(b2, b3));
            b = fmaxf(b, __shfl_xor_sync(0xffffffffu, b, 1));  // combine halves
            float newfv = b + feat;
            if (c == 0) {
                fv_sh[buf ^ 1][n] = newfv;
                if (k == 0) vbuf0 = newfv;
                else if (k == 1) vbuf1 = newfv;
                else if (k == 2) vbuf2 = newfv;
                else vbuf3 = newfv;
            }
            __syncthreads();
            buf ^= 1;
        }
        if (c == 0) {   // one aligned 128-bit store per 4 steps
            *reinterpret_cast<float4*>(sptr) =
                make_float4(vbuf0, vbuf1, vbuf2, vbuf3);
        }
        sptr += 4;
    }

    // ---------------- terminal + backtrack (warp 0) ----------------
    if (tid < 32) {
        const int l = tid;
        float fa = fv_sh[buf][l];
        float fb = (l < 16) ? fv_sh[buf][32 + l] : 0.0f;
        float sa = fa + trans_sh[STOP_TAG * KK + l];
        float sb = (l < 16) ? (fb + trans_sh[STOP_TAG * KK + 32 + l]) : PADV;
        float best;
        int tag = argmax48(sa, sb, &best);
        if (l == 0) out[seq] = best;

        // fv BEFORE step t lives at index (t-1) of the [seq][tag][*] row
        const float* rbA = g_fv + ((size_t)seq * KK + l) * TT;
        const float* rbB = g_fv + ((size_t)seq * KK + 32 + l) * TT;
        // 3-deep register prefetch of fv values
        float a0 = rbA[TT - 2];
        float e0 = (l < 16) ? rbB[TT - 2] : 0.0f;
        float a1 = rbA[TT - 3];
        float e1 = (l < 16) ? rbB[TT - 3] : 0.0f;
        float a2 = rbA[TT - 4];
        float e2 = (l < 16) ? rbB[TT - 4] : 0.0f;

#define BT_STEP(T_, AA, EE, PF)                                              \
        {                                                                    \
            if (l == 0) path_sh[(T_)] = (uint8_t)tag;                        \
            float s_a = AA + trans_sh[tag * KK + l];                         \
            float s_b = (l < 16) ? (EE + trans_sh[tag * KK + 32 + l]) : PADV;\
            int rpf = ((PF) < 1) ? 1 : (PF);                                 \
            AA = rbA[rpf - 1];                                               \
            EE = (l < 16) ? rbB[rpf - 1] : 0.0f;                             \
            float bv;                                                        \
            tag = argmax48(s_a, s_b, &bv);                                   \
        }

        for (int t = TT - 1; t >= 3; t -= 3) {   // 1023 steps, divisible by 3
            BT_STEP(t,     a0, e0, t - 3)
            BT_STEP(t - 1, a1, e1, t - 4)
            BT_STEP(t - 2, a2, e2, t - 5)
        }
        if (l == 0) path_sh[0] = (uint8_t)tag;
#undef BT_STEP
    }
    __syncthreads();

    // ---------------- coalesced path dump ----------------
    float* pout = out + BB + (size_t)seq * TT;
    for (int t = tid; t < TT; t += NT) pout[t] = (float)path_sh[t];
}

extern "C" void kernel_launch(void* const* d_in, const int* in_sizes, int n_in,
                              void* d_out, int out_size) {
    (void)in_sizes; (void)n_in; (void)out_size;
    const float* feats = (const float*)d_in[0];
    const float* trans = (const float*)d_in[1];
    float* out = (float*)d_out;
    viterbi_kernel<<<BB, NT>>>(feats, trans, out);
}